// round 1
// baseline (speedup 1.0000x reference)
#include <cuda_runtime.h>
#include <cuda_bf16.h>

// Problem: GraphSequenceOrderer_53257594470659
// B=32, K=1024, D=256. Output (f32, concatenated):
//   [0, B*K*D)           ordered_slots
//   [B*K*D, B*K*D+B*K)   order (as float)
//   [.. + B*K)           reverse_order (as float)

#define B 32
#define K 1024
#define D 256
#define NBUCKET 256   // 16x16 grid -> hilbert index in [0,256)
#define NWARP 32      // 1024 threads / 32

// int copy of order for the gather kernel (scratch; no allocations allowed)
__device__ int g_order[B * K];

__device__ __forceinline__ int hilbert_index(int x, int y) {
    int d = 0;
#pragma unroll
    for (int s = 8; s > 0; s >>= 1) {
        int rx = (x & s) ? 1 : 0;
        int ry = (y & s) ? 1 : 0;
        d += s * s * ((3 * rx) ^ ry);
        if (ry == 0) {
            if (rx == 1) {
                int t = x;
                x = s - 1 - y;
                y = s - 1 - t;
            } else {
                int t = x; x = y; y = t;
            }
        }
    }
    return d;
}

// One CTA per batch. 1024 threads, one key each.
// Stable counting sort over 256 hilbert buckets.
__global__ __launch_bounds__(1024, 1)
void sort_kernel(const float* __restrict__ centroids,
                 float* __restrict__ out_order_f,
                 float* __restrict__ out_rev_f) {
    const int b = blockIdx.x;
    const int i = threadIdx.x;
    const int lane = i & 31;
    const int warp = i >> 5;

    __shared__ int hist[NBUCKET * NWARP];  // 32 KB, bucket-major [bucket][warp]
    __shared__ int warp_sums[NWARP];

    // --- hilbert key ---
    const float2 c = ((const float2*)centroids)[b * K + i];
    float cxf = fminf(fmaxf(c.x * 15.0f, 0.0f), 15.0f);
    float cyf = fminf(fmaxf(c.y * 15.0f, 0.0f), 15.0f);
    int h = hilbert_index((int)cxf, (int)cyf);

    // --- zero histogram ---
#pragma unroll
    for (int j = 0; j < (NBUCKET * NWARP) / 1024; j++)
        hist[i + j * 1024] = 0;
    __syncthreads();

    // --- per-warp counts + stable intra-warp rank via match ---
    unsigned mask = __match_any_sync(0xffffffffu, h);
    int rank = __popc(mask & ((1u << lane) - 1u));   // # earlier lanes, same bucket
    int leader = __ffs(mask) - 1;
    if (lane == leader)
        hist[h * NWARP + warp] = __popc(mask);
    __syncthreads();

    // --- exclusive scan of 8192 entries (bucket-major => stable order) ---
    // each thread owns 8 consecutive entries
    int base = i * 8;
    int local[8];
    int lsum = 0;
#pragma unroll
    for (int j = 0; j < 8; j++) { local[j] = hist[base + j]; lsum += local[j]; }

    // block exclusive scan of lsum
    int v = lsum;
#pragma unroll
    for (int o = 1; o < 32; o <<= 1) {
        int n = __shfl_up_sync(0xffffffffu, v, o);
        if (lane >= o) v += n;
    }
    if (lane == 31) warp_sums[warp] = v;
    __syncthreads();
    if (warp == 0) {
        int w = warp_sums[lane];
        int incl = w;
#pragma unroll
        for (int o = 1; o < 32; o <<= 1) {
            int n = __shfl_up_sync(0xffffffffu, incl, o);
            if (lane >= o) incl += n;
        }
        warp_sums[lane] = incl - w;  // exclusive
    }
    __syncthreads();
    int excl = (v - lsum) + warp_sums[warp];

    int run = excl;
#pragma unroll
    for (int j = 0; j < 8; j++) {
        hist[base + j] = run;
        run += local[j];
    }
    __syncthreads();

    // --- scatter ---
    int pos = hist[h * NWARP + warp] + rank;     // stable output position
    g_order[b * K + pos] = i;
    out_order_f[b * K + pos] = (float)i;
    out_rev_f[b * K + i]   = (float)pos;
}

// Permutation gather: one warp per output row, float4 vectorized.
// 256 threads / block = 8 rows/block; grid = B*K/8 = 4096 blocks.
__global__ __launch_bounds__(256)
void gather_kernel(const float4* __restrict__ slots, float4* __restrict__ out) {
    const int row  = blockIdx.x * 8 + (threadIdx.x >> 5);  // [0, B*K)
    const int lane = threadIdx.x & 31;
    const int b = row >> 10;
    const int src = g_order[row];

    const float4* s = slots + ((size_t)(b << 10) + src) * (D / 4);
    float4*       o = out   + (size_t)row * (D / 4);
    o[lane]      = s[lane];
    o[lane + 32] = s[lane + 32];
}

extern "C" void kernel_launch(void* const* d_in, const int* in_sizes, int n_in,
                              void* d_out, int out_size) {
    const float* slots     = (const float*)d_in[0];
    // d_in[1] = adj: unused by the reference
    const float* centroids = (const float*)d_in[2];

    float* out = (float*)d_out;
    float* out_order = out + (size_t)B * K * D;
    float* out_rev   = out_order + (size_t)B * K;

    sort_kernel<<<B, 1024>>>(centroids, out_order, out_rev);
    gather_kernel<<<(B * K) / 8, 256>>>((const float4*)slots, (float4*)out);
}